// round 9
// baseline (speedup 1.0000x reference)
#include <cuda_runtime.h>
#include <cstdint>

#define BATCH 128
#define CH    32
#define LPOS  4096
#define POS   4        // positions per CTA (one per warp)
#define TPB   128
#define BB    8        // batches per group
#define NG    (BATCH / BB)             // 16 groups
#define XS_ELEMS (CH * POS * BB)       // 1024 floats per buffer (4KB)
#define WS_ELEMS (POS * CH * CH)       // 4096 floats (16KB)
#define OS_ROWS  (BB * POS)            // 32 rows
#define OS_STRIDE 33                   // conflict-free both directions

__device__ __forceinline__ unsigned long long pack2(float lo, float hi) {
    unsigned long long r;
    asm("mov.b64 %0, {%1, %2};" : "=l"(r) : "f"(lo), "f"(hi));
    return r;
}

__device__ __forceinline__ void fma2(unsigned long long& d,
                                     unsigned long long a,
                                     unsigned long long b) {
    asm("fma.rn.f32x2 %0, %1, %2, %0;" : "+l"(d) : "l"(a), "l"(b));
}

__device__ __forceinline__ uint32_t smem_u32(const void* p) {
    uint32_t a;
    asm("{ .reg .u64 t; cvta.to.shared.u64 t, %1; cvt.u32.u64 %0, t; }"
        : "=r"(a) : "l"(p));
    return a;
}

__device__ __forceinline__ void cp_async4(uint32_t dst, const float* src) {
    asm volatile("cp.async.ca.shared.global [%0], [%1], 4;\n" :: "r"(dst), "l"(src));
}
__device__ __forceinline__ void cp_async16(uint32_t dst, const float* src) {
    asm volatile("cp.async.cg.shared.global [%0], [%1], 16;\n" :: "r"(dst), "l"(src));
}

__global__ __launch_bounds__(TPB, 8)
void dyna_dec_kernel(const float* __restrict__ x,
                     const float* __restrict__ weight,
                     const float* __restrict__ bias,
                     float* __restrict__ out)
{
    // xs: [c:32][l:4][b:8], b fastest -> LDS.128 across 4 b
    __shared__ __align__(16) float xs[2][XS_ELEMS];
    // ws: [l:4][c:32][d:32] linear copy of weight rows (conflict-free LDS.32)
    __shared__ __align__(16) float ws[WS_ELEMS];
    // os: row = b*4 + l, os[row*33 + d]; STS lanes=d conflict-free; LDS row=lane conflict-free
    __shared__ __align__(16) float os[OS_ROWS * OS_STRIDE];

    const int tid  = threadIdx.x;
    const int warp = tid >> 5;       // local position l
    const int lane = tid & 31;       // output channel d
    const int l0   = blockIdx.x * POS;

    // staging decomposition: l = tid&3, b = (tid>>2)&7, c = (tid>>5) + 4k
    const int l_s = tid & 3;
    const int b_s = (tid >> 2) & 7;
    const int c0  = tid >> 5;

    const uint32_t ws_base = smem_u32(ws);
    const uint32_t xs_a0   = smem_u32(&xs[0][0]);
    const uint32_t xs_a1   = smem_u32(&xs[1][0]);

    // ---- stage weights: 4 contiguous 4KB rows = 16KB contiguous, cp.async.16 ----
    {
        const float* wsrc = weight + (size_t)l0 * (CH * CH);
#pragma unroll
        for (int k = 0; k < 8; k++) {
            int j = tid + k * TPB;               // 16B chunk id, 0..1023
            cp_async16(ws_base + j * 16, wsrc + j * 4);
        }
    }

    // ---- prologue: stage x group 0 into buffer 0 ----
    const float* gsrc = x + (size_t)b_s * (CH * LPOS) + (size_t)c0 * LPOS + l0 + l_s;
    const int dst_el = c0 * (POS * BB) + l_s * BB + b_s;   // xs element index; k step adds 128 elems (c += 4)
#pragma unroll
    for (int k = 0; k < 8; k++)
        cp_async4(xs_a0 + (dst_el + k * 4 * (POS * BB)) * 4, gsrc + (size_t)k * 4 * LPOS);
    asm volatile("cp.async.commit_group;" ::: "memory");

    const float bv = bias[(l0 + warp) * CH + lane];
    const unsigned long long bvp = pack2(bv, bv);

#pragma unroll 1
    for (int g = 0; g < NG; g++) {
        const int buf = g & 1;

        if (g + 1 < NG) {
            const float* s = gsrc + (size_t)(g + 1) * BB * (CH * LPOS);
            const uint32_t d = (buf ? xs_a0 : xs_a1);
#pragma unroll
            for (int k = 0; k < 8; k++)
                cp_async4(d + (dst_el + k * 4 * (POS * BB)) * 4, s + (size_t)k * 4 * LPOS);
            asm volatile("cp.async.commit_group;" ::: "memory");
            asm volatile("cp.async.wait_group 1;" ::: "memory");
        } else {
            asm volatile("cp.async.wait_group 0;" ::: "memory");
        }
        __syncthreads();   // xs[buf]+ws ready; prev group's os reads complete

        // ---- compute: 8 batches, lane's channel d, warp's position ----
        unsigned long long a01 = bvp, a23 = bvp, a45 = bvp, a67 = bvp;
        const ulonglong2* xp =
            reinterpret_cast<const ulonglong2*>(&xs[buf][warp * BB]);
        const float* wrow = ws + warp * (CH * CH) + lane;
#pragma unroll
        for (int c = 0; c < CH; c++) {
            float w = wrow[c * CH];                       // LDS.32 conflict-free
            unsigned long long wpp = pack2(w, w);
            ulonglong2 xv0 = xp[c * (POS * BB / 4)];      // b0..3 broadcast
            ulonglong2 xv1 = xp[c * (POS * BB / 4) + 1];  // b4..7 broadcast
            fma2(a01, xv0.x, wpp);
            fma2(a23, xv0.y, wpp);
            fma2(a45, xv1.x, wpp);
            fma2(a67, xv1.y, wpp);
        }

        // ---- stage to os: row = b*4 + warp ----
        {
            float o[8];
            asm("mov.b64 {%0, %1}, %2;" : "=f"(o[0]), "=f"(o[1]) : "l"(a01));
            asm("mov.b64 {%0, %1}, %2;" : "=f"(o[2]), "=f"(o[3]) : "l"(a23));
            asm("mov.b64 {%0, %1}, %2;" : "=f"(o[4]), "=f"(o[5]) : "l"(a45));
            asm("mov.b64 {%0, %1}, %2;" : "=f"(o[6]), "=f"(o[7]) : "l"(a67));
#pragma unroll
            for (int bb = 0; bb < BB; bb++)
                os[(bb * POS + warp) * OS_STRIDE + lane] = o[bb];
        }

        __syncthreads();   // os visible

        // ---- store out: row = b_s*4 + l_s; addr = row*33 + c0 + 4k (conflict-free) ----
        {
            const int b0g = g * BB;
            float* gdst = out + (size_t)(b0g + b_s) * (CH * LPOS)
                              + (size_t)c0 * LPOS + l0 + l_s;
            const float* osrc = os + (b_s * POS + l_s) * OS_STRIDE + c0;
#pragma unroll
            for (int k = 0; k < 8; k++)
                gdst[(size_t)k * 4 * LPOS] = osrc[k * 4];
        }
    }
}

extern "C" void kernel_launch(void* const* d_in, const int* in_sizes, int n_in,
                              void* d_out, int out_size)
{
    // metadata order: x [B,C,H,W] f32, px [1] f32 (unused), weight [L*C,C] f32, bias [L*C] f32
    const float* x      = (const float*)d_in[0];
    const float* weight = (const float*)d_in[2];
    const float* bias   = (const float*)d_in[3];
    float* out          = (float*)d_out;

    dyna_dec_kernel<<<LPOS / POS, TPB>>>(x, weight, bias, out);
}

// round 10
// speedup vs baseline: 1.2725x; 1.2725x over previous
#include <cuda_runtime.h>
#include <cstdint>

#define BATCH 128
#define CH    32
#define LPOS  4096
#define POS   8        // positions per CTA (one per warp)
#define TPB   256
#define BB    16       // batches per group
#define NG    (BATCH / BB)             // 8 groups
#define XS_ELEMS (CH * POS * BB)       // 4096 floats per buffer (16KB)
#define OS_STRIDE 164                  // per-d stride (164 % 32 == 4 -> STS.128 conflict-free)
#define OS_LMULT  20                   // per-l stride (20l+b distinct mod 32 -> LDS conflict-free)
#define SMEM_BYTES ((2 * XS_ELEMS + CH * OS_STRIDE) * 4)   // 53760

__device__ __forceinline__ unsigned long long pack2(float lo, float hi) {
    unsigned long long r;
    asm("mov.b64 %0, {%1, %2};" : "=l"(r) : "f"(lo), "f"(hi));
    return r;
}

__device__ __forceinline__ void fma2(unsigned long long& d,
                                     unsigned long long a,
                                     unsigned long long b) {
    asm("fma.rn.f32x2 %0, %1, %2, %0;" : "+l"(d) : "l"(a), "l"(b));
}

__device__ __forceinline__ uint32_t smem_u32(const void* p) {
    uint32_t a;
    asm("{ .reg .u64 t; cvta.to.shared.u64 t, %1; cvt.u32.u64 %0, t; }"
        : "=r"(a) : "l"(p));
    return a;
}

__device__ __forceinline__ void cp_async4(uint32_t dst, const float* src) {
    asm volatile("cp.async.ca.shared.global [%0], [%1], 4;\n" :: "r"(dst), "l"(src));
}

extern __shared__ float smem_dyn[];

__global__ __launch_bounds__(TPB, 4)
void dyna_dec_kernel(const float* __restrict__ x,
                     const float* __restrict__ weight,
                     const float* __restrict__ bias,
                     float* __restrict__ out)
{
    // layout: xs[2][4096] then os[CH*164]
    float* xs0 = smem_dyn;
    float* xs1 = smem_dyn + XS_ELEMS;
    float* os  = smem_dyn + 2 * XS_ELEMS;

    const int tid  = threadIdx.x;
    const int warp = tid >> 5;       // local position l
    const int lane = tid & 31;       // output channel d
    const int l0   = blockIdx.x * POS;
    const int gl   = l0 + warp;

    // ---- per-lane weights, UNPACKED (32 regs) ----
    float wp[CH];
    {
        const float* wptr = weight + (size_t)gl * (CH * CH) + lane;
#pragma unroll
        for (int c = 0; c < CH; c++) wp[c] = wptr[c * CH];
    }
    const float bv = bias[gl * CH + lane];
    const unsigned long long bvp = pack2(bv, bv);

    // ---- staging decomposition: l = tid&7, b = (tid>>3)&15, c = (tid>>7) + 2k ----
    // 8 consecutive lanes read 8 contiguous l -> full 32B sectors.
    const int l_s = tid & 7;
    const int b_s = (tid >> 3) & 15;
    const int c_s = tid >> 7;        // 0 or 1

    const float* gsrc = x + (size_t)b_s * (CH * LPOS) + (size_t)c_s * LPOS + l0 + l_s;
    // xs element index: c*128 + l*16 + b ; k-step adds 256 elems
    const int dst_el = c_s * (POS * BB) + l_s * BB + b_s;
    const uint32_t xs_a0 = smem_u32(xs0) + dst_el * 4;
    const uint32_t xs_a1 = smem_u32(xs1) + dst_el * 4;

    // prologue: stage group 0 into buffer 0
#pragma unroll
    for (int k = 0; k < 16; k++)
        cp_async4(xs_a0 + k * (2 * POS * BB * 4), gsrc + (size_t)k * 2 * LPOS);
    asm volatile("cp.async.commit_group;" ::: "memory");

#pragma unroll 1
    for (int g = 0; g < NG; g++) {
        const int buf = g & 1;

        if (g + 1 < NG) {
            const float* s = gsrc + (size_t)(g + 1) * BB * (CH * LPOS);
            const uint32_t d = (buf ? xs_a0 : xs_a1);
#pragma unroll
            for (int k = 0; k < 16; k++)
                cp_async4(d + k * (2 * POS * BB * 4), s + (size_t)k * 2 * LPOS);
            asm volatile("cp.async.commit_group;" ::: "memory");
            asm volatile("cp.async.wait_group 1;" ::: "memory");
        } else {
            asm volatile("cp.async.wait_group 0;" ::: "memory");
        }
        __syncthreads();   // xs[buf] visible; os reads of prev group complete

        // ---- compute: 16 batches, lane's channel d, warp's position ----
        unsigned long long acc[BB / 2];
#pragma unroll
        for (int j = 0; j < BB / 2; j++) acc[j] = bvp;

        const ulonglong2* xp =
            reinterpret_cast<const ulonglong2*>((buf ? xs1 : xs0) + warp * BB);
        // ull2 index: warp*4 + c*32 + j  (all lanes same addr -> broadcast LDS.128)
#pragma unroll
        for (int c = 0; c < CH; c++) {
            const unsigned long long wpp = pack2(wp[c], wp[c]);
            const ulonglong2* xc = xp + c * (POS * BB / 4);
#pragma unroll
            for (int j = 0; j < 4; j++) {
                ulonglong2 xv = xc[j];
                fma2(acc[2 * j],     xv.x, wpp);
                fma2(acc[2 * j + 1], xv.y, wpp);
            }
        }

        // ---- stage to os: os[lane*164 + warp*20 + b], 4x STS.128 ----
        {
            float* op = os + lane * OS_STRIDE + warp * OS_LMULT;
#pragma unroll
            for (int j = 0; j < 4; j++) {
                float4 ov;
                asm("mov.b64 {%0, %1}, %2;" : "=f"(ov.x), "=f"(ov.y) : "l"(acc[2 * j]));
                asm("mov.b64 {%0, %1}, %2;" : "=f"(ov.z), "=f"(ov.w) : "l"(acc[2 * j + 1]));
                *reinterpret_cast<float4*>(op + 4 * j) = ov;
            }
        }

        __syncthreads();   // os visible across warps

        // ---- store out: same (l,b) decomposition, d = c_s + 2k ----
        {
            float* gdst = out + (size_t)(g * BB + b_s) * (CH * LPOS)
                              + (size_t)c_s * LPOS + l0 + l_s;
            const float* osrc = os + c_s * OS_STRIDE + l_s * OS_LMULT + b_s;
#pragma unroll
            for (int k = 0; k < 16; k++)
                gdst[(size_t)k * 2 * LPOS] = osrc[k * 2 * OS_STRIDE];
        }
    }
}

extern "C" void kernel_launch(void* const* d_in, const int* in_sizes, int n_in,
                              void* d_out, int out_size)
{
    // metadata order: x [B,C,H,W] f32, px [1] f32 (unused), weight [L*C,C] f32, bias [L*C] f32
    const float* x      = (const float*)d_in[0];
    const float* weight = (const float*)d_in[2];
    const float* bias   = (const float*)d_in[3];
    float* out          = (float*)d_out;

    cudaFuncSetAttribute(dyna_dec_kernel,
                         cudaFuncAttributeMaxDynamicSharedMemorySize, SMEM_BYTES);
    dyna_dec_kernel<<<LPOS / POS, TPB, SMEM_BYTES>>>(x, weight, bias, out);
}

// round 14
// speedup vs baseline: 1.4711x; 1.1561x over previous
#include <cuda_runtime.h>
#include <cstdint>

#define BATCH 128
#define CH    32
#define LPOS  4096
#define POS   4        // positions per CTA (one per warp)
#define TPB   128
#define BB    8        // batches per group
#define NG    (BATCH / BB)             // 16 groups
#define XS_ELEMS (CH * POS * BB)       // 1024 floats per buffer (4KB)
#define OS_STRIDE 36                   // per-d stride: 36%32==4 -> conflict-free both sides

__device__ __forceinline__ unsigned long long pack2(float lo, float hi) {
    unsigned long long r;
    asm("mov.b64 %0, {%1, %2};" : "=l"(r) : "f"(lo), "f"(hi));
    return r;
}

__device__ __forceinline__ void fma2(unsigned long long& d,
                                     unsigned long long a,
                                     unsigned long long b) {
    asm("fma.rn.f32x2 %0, %1, %2, %0;" : "+l"(d) : "l"(a), "l"(b));
}

__device__ __forceinline__ uint32_t smem_u32(const void* p) {
    uint32_t a;
    asm("{ .reg .u64 t; cvta.to.shared.u64 t, %1; cvt.u32.u64 %0, t; }"
        : "=r"(a) : "l"(p));
    return a;
}

__device__ __forceinline__ void cp_async4(uint32_t dst, const float* src) {
    asm volatile("cp.async.ca.shared.global [%0], [%1], 4;\n" :: "r"(dst), "l"(src));
}

__global__ __launch_bounds__(TPB, 8)
void dyna_dec_kernel(const float* __restrict__ x,
                     const float* __restrict__ weight,
                     const float* __restrict__ bias,
                     float* __restrict__ out)
{
    // xs: [c:32][l:4][b:8], b fastest -> 2x broadcast LDS.128 per c
    __shared__ __align__(16) float xs[2][XS_ELEMS];
    // os: [d][l][b] = d*36 + l*8 + b
    //   STS.128 (lane=d): 36d mod 32 = 4d -> 8-lane phases distinct ✓
    //   LDS.32 store side (d const/warp, 4l x 8b lanes): 8l+b all distinct mod 32 ✓
    __shared__ __align__(16) float os[CH * OS_STRIDE];

    const int tid  = threadIdx.x;
    const int warp = tid >> 5;       // local position l (0..3)
    const int lane = tid & 31;       // output channel d
    const int l0   = blockIdx.x * POS;
    const int gl   = l0 + warp;

    // ---- per-lane weights, UNPACKED (32 regs); coalesced 128B per c ----
    float wp[CH];
    {
        const float* wptr = weight + (size_t)gl * (CH * CH) + lane;
#pragma unroll
        for (int c = 0; c < CH; c++) wp[c] = wptr[c * CH];
    }
    const float bv = bias[gl * CH + lane];
    const unsigned long long bvp = pack2(bv, bv);

    // ---- staging decomposition: i = tid + 128k -> l=i&3, b=(i>>2)&7, c=(i>>5) ----
    const int l_s = tid & 3;
    const int b_s = (tid >> 2) & 7;
    const int c0  = tid >> 5;        // 0..3 ; c = c0 + 4k

    const float* gsrc = x + (size_t)b_s * (CH * LPOS) + (size_t)c0 * LPOS + l0 + l_s;
    const int dst_el = c0 * (POS * BB) + l_s * BB + b_s;   // k-step adds 128 elems
    const uint32_t xs_a0 = smem_u32(&xs[0][0]) + dst_el * 4;
    const uint32_t xs_a1 = smem_u32(&xs[1][0]) + dst_el * 4;

    // prologue: stage group 0 into buffer 0
#pragma unroll
    for (int k = 0; k < 8; k++)
        cp_async4(xs_a0 + k * (4 * POS * BB * 4), gsrc + (size_t)k * 4 * LPOS);
    asm volatile("cp.async.commit_group;" ::: "memory");

#pragma unroll 1
    for (int g = 0; g < NG; g++) {
        const int buf = g & 1;

        if (g + 1 < NG) {
            const float* s = gsrc + (size_t)(g + 1) * BB * (CH * LPOS);
            const uint32_t d = (buf ? xs_a0 : xs_a1);
#pragma unroll
            for (int k = 0; k < 8; k++)
                cp_async4(d + k * (4 * POS * BB * 4), s + (size_t)k * 4 * LPOS);
            asm volatile("cp.async.commit_group;" ::: "memory");
            asm volatile("cp.async.wait_group 1;" ::: "memory");
        } else {
            asm volatile("cp.async.wait_group 0;" ::: "memory");
        }
        __syncthreads();   // xs[buf] visible; os reads of prev group complete

        // ---- compute: 8 batches, lane's channel d, warp's position ----
        unsigned long long a01 = bvp, a23 = bvp, a45 = bvp, a67 = bvp;
        const ulonglong2* xp =
            reinterpret_cast<const ulonglong2*>(&xs[buf][warp * BB]);
        // ull2 index: warp*2 + c*8 (+1) ; all lanes same addr -> broadcast LDS.128
#pragma unroll
        for (int c = 0; c < CH; c++) {
            const unsigned long long wpp = pack2(wp[c], wp[c]);
            ulonglong2 xv0 = xp[c * (POS * BB / 4)];       // b0..3
            ulonglong2 xv1 = xp[c * (POS * BB / 4) + 1];   // b4..7
            fma2(a01, xv0.x, wpp);
            fma2(a23, xv0.y, wpp);
            fma2(a45, xv1.x, wpp);
            fma2(a67, xv1.y, wpp);
        }

        // ---- stage to os: 2x STS.128 at os[lane*36 + warp*8] ----
        {
            float4 o0, o1;
            asm("mov.b64 {%0, %1}, %2;" : "=f"(o0.x), "=f"(o0.y) : "l"(a01));
            asm("mov.b64 {%0, %1}, %2;" : "=f"(o0.z), "=f"(o0.w) : "l"(a23));
            asm("mov.b64 {%0, %1}, %2;" : "=f"(o1.x), "=f"(o1.y) : "l"(a45));
            asm("mov.b64 {%0, %1}, %2;" : "=f"(o1.z), "=f"(o1.w) : "l"(a67));
            float* op = os + lane * OS_STRIDE + warp * BB;
            *reinterpret_cast<float4*>(op)     = o0;
            *reinterpret_cast<float4*>(op + 4) = o1;
        }

        __syncthreads();   // os visible across warps

        // ---- store out: same (l,b,c) decomposition; LDS.32 conflict-free ----
        {
            float* gdst = out + (size_t)(g * BB + b_s) * (CH * LPOS)
                              + (size_t)c0 * LPOS + l0 + l_s;
            const float* osrc = os + c0 * OS_STRIDE + l_s * BB + b_s;
#pragma unroll
            for (int k = 0; k < 8; k++)
                gdst[(size_t)k * 4 * LPOS] = osrc[k * 4 * OS_STRIDE];
        }
    }
}

extern "C" void kernel_launch(void* const* d_in, const int* in_sizes, int n_in,
                              void* d_out, int out_size)
{
    // metadata order: x [B,C,H,W] f32, px [1] f32 (unused), weight [L*C,C] f32, bias [L*C] f32
    const float* x      = (const float*)d_in[0];
    const float* weight = (const float*)d_in[2];
    const float* bias   = (const float*)d_in[3];
    float* out          = (float*)d_out;

    dyna_dec_kernel<<<LPOS / POS, TPB>>>(x, weight, bias, out);
}